// round 15
// baseline (speedup 1.0000x reference)
#include <cuda_runtime.h>
#include <cuda_bf16.h>
#include <cstdint>

#define N_NODES 100000
#define N_EDGES 640000
#define DD      128
#define ROUNDS  4
#define SCAN_BLOCKS 98            // ceil(100000 / 1024)

// chunking: 1563 M-blocks total -> 782 (rows [0,50048)) + 781 (rows [50048,100000))
#define CHUNK_BLKS0 782
#define CHUNK_BLKS1 781
#define CHUNK_ROWS0 50048

// ---------------- scratch (allocation-free rule: __device__ globals) ----------------
__device__ __align__(16) float g_msg[N_NODES * DD];
// interleaved split-bf16 tensors: per node 128 hi then 128 lo (512B/node)
__device__ __align__(16) __nv_bfloat16 g_aggbf[N_NODES * 2 * DD];
__device__ __align__(16) __nv_bfloat16 g_statebf[N_NODES * 2 * DD];
__device__ __align__(16) __nv_bfloat16 g_wb[9 * 2 * 16384];
__device__ int g_idx64;
// CSR build scratch
__device__ int g_deg[N_NODES];
__device__ int g_off[N_NODES + 1];
__device__ int g_cur[N_NODES];
__device__ int g_srcs[N_EDGES];
__device__ int g_bsum[SCAN_BLOCKS];
__device__ int g_boff[SCAN_BLOCKS];

// ---------------- edge_index dtype detection ----------------
__global__ void detect_idx_kernel(const int* __restrict__ ei32) {
    int is64 = 1;
    for (int i = 0; i < 32; i++) {
        int lo = ei32[2 * i];
        int hi = ei32[2 * i + 1];
        if (hi != 0 || lo < 0 || lo >= N_NODES) { is64 = 0; break; }
    }
    g_idx64 = is64;
}

// ---------------- CSR build (once per call, overlapped with first GEMMs) ----------------
__global__ void hist_zero_kernel() {
    int i = blockIdx.x * blockDim.x + threadIdx.x;
    if (i < N_NODES) g_deg[i] = 0;
}

__device__ __forceinline__ int edge_dst(const void* ei_raw, int e) {
    if (g_idx64) return (int)((const long long*)ei_raw)[N_EDGES + e];
    return ((const int*)ei_raw)[N_EDGES + e];
}
__device__ __forceinline__ int edge_src(const void* ei_raw, int e) {
    if (g_idx64) return (int)((const long long*)ei_raw)[e];
    return ((const int*)ei_raw)[e];
}

__global__ void hist_kernel(const void* __restrict__ ei_raw) {
    int e = blockIdx.x * blockDim.x + threadIdx.x;
    if (e >= N_EDGES) return;
    int d = edge_dst(ei_raw, e);
    if ((unsigned)d < N_NODES) atomicAdd(&g_deg[d], 1);
}

__global__ void scan1_kernel() {
    __shared__ int ss[256];
    int b = blockIdx.x, t = threadIdx.x;
    int base = b * 1024 + t * 4;
    int v[4], tot = 0;
#pragma unroll
    for (int j = 0; j < 4; j++) {
        v[j] = (base + j < N_NODES) ? g_deg[base + j] : 0;
        tot += v[j];
    }
    ss[t] = tot;
    __syncthreads();
#pragma unroll
    for (int off = 1; off < 256; off <<= 1) {
        int x = (t >= off) ? ss[t - off] : 0;
        __syncthreads();
        ss[t] += x;
        __syncthreads();
    }
    int run = ss[t] - tot;
#pragma unroll
    for (int j = 0; j < 4; j++) {
        if (base + j < N_NODES) g_off[base + j] = run;
        run += v[j];
    }
    if (t == 255) g_bsum[b] = ss[255];
}

__global__ void scan2_kernel() {
    __shared__ int ss[128];
    int t = threadIdx.x;
    int orig = (t < SCAN_BLOCKS) ? g_bsum[t] : 0;
    ss[t] = orig;
    __syncthreads();
#pragma unroll
    for (int off = 1; off < 128; off <<= 1) {
        int x = (t >= off) ? ss[t - off] : 0;
        __syncthreads();
        ss[t] += x;
        __syncthreads();
    }
    if (t < SCAN_BLOCKS) g_boff[t] = ss[t] - orig;
}

__global__ void scan3_kernel() {
    int i = blockIdx.x * blockDim.x + threadIdx.x;
    if (i < N_NODES) {
        int o = g_off[i] + g_boff[i >> 10];
        g_off[i] = o;
        g_cur[i] = o;
    }
    if (i == 0) g_off[N_NODES] = N_EDGES;
}

__global__ void fill_kernel(const void* __restrict__ ei_raw) {
    int e = blockIdx.x * blockDim.x + threadIdx.x;
    if (e >= N_EDGES) return;
    int d = edge_dst(ei_raw, e);
    int s = edge_src(ei_raw, e);
    if ((unsigned)d >= N_NODES || (unsigned)s >= N_NODES) return;
    int p = atomicAdd(&g_cur[d], 1);
    g_srcs[p] = s;
}

// ---------------- per-round aggregation: gather fp32 msg, write split-bf16 agg ----------------
__global__ __launch_bounds__(256) void aggregate_kernel(int node_lo, int node_hi) {
    int node = node_lo + ((blockIdx.x * 256 + threadIdx.x) >> 5);
    int lane = threadIdx.x & 31;
    if (node >= node_hi) return;
    int beg = g_off[node], end = g_off[node + 1];
    float4 acc = make_float4(0.f, 0.f, 0.f, 0.f);
    int e = beg;
    for (; e + 1 < end; e += 2) {
        int s0 = g_srcs[e], s1 = g_srcs[e + 1];
        float4 v0 = *(const float4*)(g_msg + (size_t)s0 * DD + lane * 4);
        float4 v1 = *(const float4*)(g_msg + (size_t)s1 * DD + lane * 4);
        acc.x += v0.x; acc.y += v0.y; acc.z += v0.z; acc.w += v0.w;
        acc.x += v1.x; acc.y += v1.y; acc.z += v1.z; acc.w += v1.w;
    }
    if (e < end) {
        float4 v = *(const float4*)(g_msg + (size_t)g_srcs[e] * DD + lane * 4);
        acc.x += v.x; acc.y += v.y; acc.z += v.z; acc.w += v.w;
    }
    float vv[4] = {acc.x, acc.y, acc.z, acc.w};
    __align__(8) __nv_bfloat16 h[4], l[4];
#pragma unroll
    for (int j = 0; j < 4; j++) {
        h[j] = __float2bfloat16(vv[j]);
        l[j] = __float2bfloat16(vv[j] - __bfloat162float(h[j]));
    }
    __nv_bfloat16* base = g_aggbf + (size_t)node * (2 * DD);
    *(uint2*)(base + lane * 4)      = *(const uint2*)h;   // hi image [0,128)
    *(uint2*)(base + DD + lane * 4) = *(const uint2*)l;   // lo image [128,256)
}

// ---------------- weight precompute: transpose + bf16 split ----------------
__global__ void conv_w_kernel(const float* __restrict__ Wi,
                              const float* __restrict__ Wm,
                              const float* __restrict__ Wu) {
    int m = blockIdx.x;  // 0..8
    const float* W = (m == 0) ? Wi : (m <= 4 ? Wm + (m - 1) * DD * DD : Wu + (m - 5) * DD * DD);
    __nv_bfloat16* hi = g_wb + (size_t)m * 32768;
    __nv_bfloat16* lo = hi + 16384;
    for (int i = threadIdx.x; i < 2048; i += blockDim.x) {
        int nrow = i >> 4;
        int k8   = (i & 15) * 8;
        __align__(16) __nv_bfloat16 h[8], l[8];
#pragma unroll
        for (int j = 0; j < 8; j++) {
            float w = W[(size_t)(k8 + j) * DD + nrow];   // B[n][k] = W[k][n]
            __nv_bfloat16 hb = __float2bfloat16(w);
            h[j] = hb;
            l[j] = __float2bfloat16(w - __bfloat162float(hb));
        }
        *(uint4*)(hi + nrow * DD + k8) = *(const uint4*)h;
        *(uint4*)(lo + nrow * DD + k8) = *(const uint4*)l;
    }
}

// ---------------- helpers (base-target PTX only) ----------------
__device__ __forceinline__ uint32_t smem_u32(const void* p) {
    uint32_t a;
    asm("{ .reg .u64 t; cvta.to.shared.u64 t, %1; cvt.u32.u64 %0, t; }" : "=r"(a) : "l"(p));
    return a;
}
__device__ __forceinline__ void ldsm4(uint32_t* r, uint32_t addr) {
    asm volatile("ldmatrix.sync.aligned.m8n8.x4.shared.b16 {%0,%1,%2,%3}, [%4];"
                 : "=r"(r[0]), "=r"(r[1]), "=r"(r[2]), "=r"(r[3]) : "r"(addr));
}
__device__ __forceinline__ void mma_bf16(float* c,
                                         const uint32_t* a, uint32_t b0, uint32_t b1) {
    asm volatile(
        "mma.sync.aligned.m16n8k16.row.col.f32.bf16.bf16.f32 "
        "{%0,%1,%2,%3}, {%4,%5,%6,%7}, {%8,%9}, {%0,%1,%2,%3};"
        : "+f"(c[0]), "+f"(c[1]), "+f"(c[2]), "+f"(c[3])
        : "r"(a[0]), "r"(a[1]), "r"(a[2]), "r"(a[3]), "r"(b0), "r"(b1));
}
__device__ __forceinline__ void cp_async16(uint32_t smem_addr, const void* gptr) {
    asm volatile("cp.async.ca.shared.global [%0], [%1], 16;"
                 :: "r"(smem_addr), "l"(gptr) : "memory");
}
__device__ __forceinline__ void cp_async16z(uint32_t smem_addr, const void* gptr, unsigned srcsz) {
    asm volatile("cp.async.ca.shared.global [%0], [%1], 16, %2;"
                 :: "r"(smem_addr), "l"(gptr), "r"(srcsz) : "memory");
}

// ---------------- GEMM: 64x128 tile, 2 CTAs/SM, pipelined frags ----------------
#define TILE_M  64
#define BSTR    136
#define A_TB    (TILE_M * BSTR * 2)       // 17408 B
#define B_TB    (128 * BSTR * 2)          // 34816 B
#define SM_BIAS 0
#define SM_AHI  512
#define SM_ALO  (SM_AHI + A_TB)
#define SM_BHI  (SM_ALO + A_TB)
#define SM_BLO  (SM_BHI + B_TB)
#define SM_TOTAL (SM_BLO + B_TB)          // 104960 B -> 2 CTAs/SM

// MODE: 0 fresh / 1 residual (out += ...)
// ASRC: 0 = fp32 A (convert in-kernel), 1 = interleaved split-bf16 A via cp.async
// WFP:  write fp32 result to out
// WBF:  also write interleaved split-bf16 result to obf (state for next GEMM)
template <int MODE, int ASRC, int WFP, int WBF>
__global__ __launch_bounds__(256, 2) void gemm_mma_kernel(
    const float* __restrict__ A,
    const __nv_bfloat16* __restrict__ abf,
    const __nv_bfloat16* __restrict__ wb,
    const float* __restrict__ bias,
    float* __restrict__ out,
    __nv_bfloat16* __restrict__ obf,
    int n, int mb0)
{
    extern __shared__ char smem[];
    const uint32_t sb = smem_u32(smem);
    const int tid = threadIdx.x, wid = tid >> 5, lane = tid & 31;
    const int wr = wid & 1, wc = wid >> 1;      // warp grid 2 (M) x 4 (N)
    const int m0 = (blockIdx.x + mb0) * TILE_M;

    if (tid < 128) *(float*)(smem + SM_BIAS + tid * 4) = bias[tid];

    // ---- B tiles via cp.async ----
    {
        const uint4* srch = (const uint4*)wb;
        const uint4* srcl = (const uint4*)(wb + 16384);
#pragma unroll
        for (int i = tid; i < 2048; i += 256) {
            int row = i >> 4, c = i & 15;
            uint32_t doff = (uint32_t)(row * (BSTR * 2) + c * 16);
            cp_async16(sb + SM_BHI + doff, srch + row * 16 + c);
            cp_async16(sb + SM_BLO + doff, srcl + row * 16 + c);
        }
    }

    if (ASRC == 1) {
        // ---- A tiles: pure cp.async of interleaved split-bf16 (zfill on tail) ----
#pragma unroll
        for (int i = tid; i < 1024; i += 256) {
            int r = i >> 4, c = i & 15;      // c: 16B chunk (8 bf16) within 256B image
            int row = m0 + r;
            int crow = row < n ? row : 0;
            unsigned sz = (row < n) ? 16u : 0u;
            uint32_t doff = (uint32_t)(r * (BSTR * 2) + c * 16);
            const __nv_bfloat16* base = abf + (size_t)crow * (2 * DD) + c * 8;
            cp_async16z(sb + SM_AHI + doff, base, sz);
            cp_async16z(sb + SM_ALO + doff, base + DD, sz);
        }
        asm volatile("cp.async.commit_group;" ::: "memory");
    } else {
        asm volatile("cp.async.commit_group;" ::: "memory");
        // ---- A tile: fp32 -> bf16 hi/lo in-kernel ----
        for (int i = tid; i < TILE_M * 16; i += 256) {
            int r  = i >> 4;
            int k8 = (i & 15) * 8;
            int row = m0 + r;
            float v[8];
            if (row < n) {
                float4 u0 = *(const float4*)(A + (size_t)row * DD + k8);
                float4 u1 = *(const float4*)(A + (size_t)row * DD + k8 + 4);
                v[0] = u0.x; v[1] = u0.y; v[2] = u0.z; v[3] = u0.w;
                v[4] = u1.x; v[5] = u1.y; v[6] = u1.z; v[7] = u1.w;
            } else {
#pragma unroll
                for (int j = 0; j < 8; j++) v[j] = 0.f;
            }
            __align__(16) __nv_bfloat16 h[8], l[8];
#pragma unroll
            for (int j = 0; j < 8; j++) {
                __nv_bfloat16 hb = __float2bfloat16(v[j]);
                h[j] = hb;
                l[j] = __float2bfloat16(v[j] - __bfloat162float(hb));
            }
            *(uint4*)(smem + SM_AHI + r * (BSTR * 2) + k8 * 2) = *(const uint4*)h;
            *(uint4*)(smem + SM_ALO + r * (BSTR * 2) + k8 * 2) = *(const uint4*)l;
        }
    }
    asm volatile("cp.async.wait_group 0;" ::: "memory");
    __syncthreads();

    // ---- mainloop: 8 k-steps, double-buffered frags ----
    float acc[2][4][4];
#pragma unroll
    for (int t = 0; t < 2; t++)
#pragma unroll
        for (int j = 0; j < 4; j++)
#pragma unroll
            for (int q = 0; q < 4; q++)
                acc[t][j][q] = 0.f;

    const uint32_t a_row  = (uint32_t)(wr * 32 + (lane & 15));
    const uint32_t a_colh = (uint32_t)(lane >> 4);
    const uint32_t b_nrow = (uint32_t)(wc * 32 + (lane & 7) + ((lane >> 4) << 3));
    const uint32_t b_kh   = (uint32_t)((lane >> 3) & 1);

    uint32_t ah[2][2][4], al[2][2][4], bh[2][2][4], bl[2][2][4];

#define LOAD_K(ks_, buf_)                                                          \
    {                                                                              \
        const uint32_t kcol = (uint32_t)((ks_) * 16);                              \
        _Pragma("unroll")                                                          \
        for (int t = 0; t < 2; t++) {                                              \
            uint32_t off = (a_row + t * 16) * (BSTR * 2) + (kcol + a_colh * 8) * 2;\
            ldsm4(ah[buf_][t], sb + SM_AHI + off);                                 \
            ldsm4(al[buf_][t], sb + SM_ALO + off);                                 \
        }                                                                          \
        _Pragma("unroll")                                                          \
        for (int p = 0; p < 2; p++) {                                              \
            uint32_t off = (b_nrow + p * 16) * (BSTR * 2) + (kcol + b_kh * 8) * 2; \
            ldsm4(bh[buf_][p], sb + SM_BHI + off);                                 \
            ldsm4(bl[buf_][p], sb + SM_BLO + off);                                 \
        }                                                                          \
    }

    LOAD_K(0, 0)
#pragma unroll
    for (int ks = 0; ks < 8; ks++) {
        const int cur = ks & 1;
        if (ks < 7) LOAD_K(ks + 1, cur ^ 1)
#pragma unroll
        for (int t = 0; t < 2; t++) {
#pragma unroll
            for (int j = 0; j < 4; j++) {
                uint32_t b0h = bh[cur][j >> 1][(j & 1) * 2], b1h = bh[cur][j >> 1][(j & 1) * 2 + 1];
                uint32_t b0l = bl[cur][j >> 1][(j & 1) * 2], b1l = bl[cur][j >> 1][(j & 1) * 2 + 1];
                float* c = acc[t][j];
                mma_bf16(c, ah[cur][t], b0h, b1h);
                mma_bf16(c, ah[cur][t], b0l, b1l);
                mma_bf16(c, al[cur][t], b0h, b1h);
            }
        }
    }
#undef LOAD_K

    // ---- epilogue: bias + relu (+ residual), write fp32 and/or split-bf16 ----
    const float* bs = (const float*)(smem + SM_BIAS);
#pragma unroll
    for (int t = 0; t < 2; t++) {
        int row0 = m0 + wr * 32 + t * 16 + (lane >> 2);
#pragma unroll
        for (int half = 0; half < 2; half++) {
            int row = row0 + half * 8;
            if (row >= n) continue;
            float* orow = out + (size_t)row * DD;
            __nv_bfloat16* brow = obf + (size_t)row * (2 * DD);
#pragma unroll
            for (int j = 0; j < 4; j++) {
                int col = wc * 32 + j * 8 + (lane & 3) * 2;
                float v0 = acc[t][j][half * 2 + 0] + bs[col];
                float v1 = acc[t][j][half * 2 + 1] + bs[col + 1];
                v0 = v0 > 0.f ? v0 : 0.f;
                v1 = v1 > 0.f ? v1 : 0.f;
                if (MODE == 1) {
                    float2 o = *(const float2*)(orow + col);
                    v0 += o.x; v1 += o.y;
                }
                if (WFP)
                    *(float2*)(orow + col) = make_float2(v0, v1);
                if (WBF) {
                    __nv_bfloat16 h0 = __float2bfloat16(v0);
                    __nv_bfloat16 h1 = __float2bfloat16(v1);
                    __nv_bfloat16 l0 = __float2bfloat16(v0 - __bfloat162float(h0));
                    __nv_bfloat16 l1 = __float2bfloat16(v1 - __bfloat162float(h1));
                    __nv_bfloat16 hh[2] = {h0, h1}, ll[2] = {l0, l1};
                    *(uint32_t*)(brow + col)      = *(const uint32_t*)hh;
                    *(uint32_t*)(brow + DD + col) = *(const uint32_t*)ll;
                }
            }
        }
    }
}

// ---------------- launcher: ONE side stream = CSR build then chunk-B chain ----------------
extern "C" void kernel_launch(void* const* d_in, const int* in_sizes, int n_in,
                              void* d_out, int out_size)
{
    const float* x  = (const float*)d_in[0];
    const void*  ei = d_in[1];
    const float* Wi = (const float*)d_in[2];
    const float* bi = (const float*)d_in[3];
    const float* Wm = (const float*)d_in[4];
    const float* bm = (const float*)d_in[5];
    const float* Wu = (const float*)d_in[6];
    const float* bu = (const float*)d_in[7];
    float* out = (float*)d_out;

    cudaFuncSetAttribute(gemm_mma_kernel<0,0,1,1>, cudaFuncAttributeMaxDynamicSharedMemorySize, SM_TOTAL);
    cudaFuncSetAttribute(gemm_mma_kernel<0,1,1,0>, cudaFuncAttributeMaxDynamicSharedMemorySize, SM_TOTAL);
    cudaFuncSetAttribute(gemm_mma_kernel<1,1,1,1>, cudaFuncAttributeMaxDynamicSharedMemorySize, SM_TOTAL);

    float* msg;
    __nv_bfloat16 *wb, *aggbf, *statebf;
    cudaGetSymbolAddress((void**)&msg, g_msg);
    cudaGetSymbolAddress((void**)&wb, g_wb);
    cudaGetSymbolAddress((void**)&aggbf, g_aggbf);
    cudaGetSymbolAddress((void**)&statebf, g_statebf);

    const int GRID_FULL = (N_NODES + TILE_M - 1) / TILE_M;   // 1563
    const int AGG_G0 = (CHUNK_ROWS0 * 32 + 255) / 256;
    const int AGG_G1 = ((N_NODES - CHUNK_ROWS0) * 32 + 255) / 256;

    cudaStream_t s3;
    cudaStreamCreateWithFlags(&s3, cudaStreamNonBlocking);
    cudaEvent_t e0, e1, eM0, evA[ROUNDS], evB[ROUNDS];
    cudaEventCreateWithFlags(&e0, cudaEventDisableTiming);
    cudaEventCreateWithFlags(&e1, cudaEventDisableTiming);
    cudaEventCreateWithFlags(&eM0, cudaEventDisableTiming);
    for (int r = 0; r < ROUNDS; r++) {
        cudaEventCreateWithFlags(&evA[r], cudaEventDisableTiming);
        cudaEventCreateWithFlags(&evB[r], cudaEventDisableTiming);
    }

    // ---- side stream: CSR build (overlaps first GEMMs), then chunk-B chain ----
    cudaEventRecord(e0, 0);
    cudaStreamWaitEvent(s3, e0, 0);
    detect_idx_kernel<<<1, 1, 0, s3>>>((const int*)ei);
    hist_zero_kernel<<<(N_NODES + 255) / 256, 256, 0, s3>>>();
    hist_kernel<<<(N_EDGES + 255) / 256, 256, 0, s3>>>(ei);
    scan1_kernel<<<SCAN_BLOCKS, 256, 0, s3>>>();
    scan2_kernel<<<1, 128, 0, s3>>>();
    scan3_kernel<<<(N_NODES + 255) / 256, 256, 0, s3>>>();
    fill_kernel<<<(N_EDGES + 255) / 256, 256, 0, s3>>>(ei);
    cudaEventRecord(e1, s3);            // CSR ready

    // ---- main chain: weights, input GEMM (fp32 A; writes out + statebf), msg GEMM ----
    conv_w_kernel<<<9, 256>>>(Wi, Wm, Wu);
    gemm_mma_kernel<0,0,1,1><<<GRID_FULL, 256, SM_TOTAL>>>(
        x, nullptr, wb, bi, out, statebf, N_NODES, 0);
    gemm_mma_kernel<0,1,1,0><<<GRID_FULL, 256, SM_TOTAL>>>(
        nullptr, statebf, wb + 32768, bm, msg, statebf /*unused*/, N_NODES, 0);

    cudaStreamWaitEvent(0, e1, 0);       // main: CSR must be built before aggregate A
    cudaEventRecord(eM0, 0);
    cudaStreamWaitEvent(s3, eM0, 0);     // s3: msg ready (CSR already done in s3 order)

    for (int r = 0; r < ROUNDS; r++) {
        // chain A (default stream): chunk 0 = rows [0, CHUNK_ROWS0)
        aggregate_kernel<<<AGG_G0, 256>>>(0, CHUNK_ROWS0);
        gemm_mma_kernel<1,1,1,1><<<CHUNK_BLKS0, 256, SM_TOTAL>>>(
            nullptr, aggbf, wb + (size_t)(5 + r) * 32768, bu + r * DD, out, statebf, N_NODES, 0);
        if (r + 1 < ROUNDS)
            gemm_mma_kernel<0,1,1,0><<<CHUNK_BLKS0, 256, SM_TOTAL>>>(
                nullptr, statebf, wb + (size_t)(2 + r) * 32768, bm + (r + 1) * DD,
                msg, statebf /*unused*/, N_NODES, 0);

        // chain B (s3): chunk 1 = rows [CHUNK_ROWS0, N_NODES)
        aggregate_kernel<<<AGG_G1, 256, 0, s3>>>(CHUNK_ROWS0, N_NODES);
        gemm_mma_kernel<1,1,1,1><<<CHUNK_BLKS1, 256, SM_TOTAL, s3>>>(
            nullptr, aggbf, wb + (size_t)(5 + r) * 32768, bu + r * DD, out, statebf,
            N_NODES, CHUNK_BLKS0);
        if (r + 1 < ROUNDS)
            gemm_mma_kernel<0,1,1,0><<<CHUNK_BLKS1, 256, SM_TOTAL, s3>>>(
                nullptr, statebf, wb + (size_t)(2 + r) * 32768, bm + (r + 1) * DD,
                msg, statebf /*unused*/, N_NODES, CHUNK_BLKS0);

        // join: next round's aggregates read ALL msg rows; final round: out complete on main
        cudaEventRecord(evB[r], s3);
        cudaStreamWaitEvent(0, evB[r], 0);
        if (r + 1 < ROUNDS) {
            cudaEventRecord(evA[r], 0);
            cudaStreamWaitEvent(s3, evA[r], 0);
        }
    }
}

// round 16
// speedup vs baseline: 1.1004x; 1.1004x over previous
#include <cuda_runtime.h>
#include <cuda_bf16.h>
#include <cstdint>

#define N_NODES 100000
#define N_EDGES 640000
#define DD      128
#define ROUNDS  4
#define SCAN_BLOCKS 98            // ceil(100000 / 1024)

// chunking: 1563 M-blocks total -> 782 (rows [0,50048)) + 781 (rows [50048,100000))
#define CHUNK_BLKS0 782
#define CHUNK_BLKS1 781
#define CHUNK_ROWS0 50048

// ---------------- scratch (allocation-free rule: __device__ globals) ----------------
__device__ __align__(16) float g_msg[N_NODES * DD];
// interleaved split-bf16 tensors: per node 128 hi then 128 lo (512B/node)
__device__ __align__(16) __nv_bfloat16 g_aggbf[N_NODES * 2 * DD];
__device__ __align__(16) __nv_bfloat16 g_statebf[N_NODES * 2 * DD];
__device__ __align__(16) __nv_bfloat16 g_wb[9 * 2 * 16384];
__device__ int g_idx64;
// CSR build scratch
__device__ int g_deg[N_NODES];
__device__ int g_off[N_NODES + 1];
__device__ int g_cur[N_NODES];
__device__ int g_srcs[N_EDGES];
__device__ int g_bsum[SCAN_BLOCKS];
__device__ int g_boff[SCAN_BLOCKS];

// ---------------- edge_index dtype detection ----------------
__global__ void detect_idx_kernel(const int* __restrict__ ei32) {
    int is64 = 1;
    for (int i = 0; i < 32; i++) {
        int lo = ei32[2 * i];
        int hi = ei32[2 * i + 1];
        if (hi != 0 || lo < 0 || lo >= N_NODES) { is64 = 0; break; }
    }
    g_idx64 = is64;
}

// ---------------- CSR build (once per call, overlapped with first GEMMs) ----------------
__global__ void hist_zero_kernel() {
    int i = blockIdx.x * blockDim.x + threadIdx.x;
    if (i < N_NODES) g_deg[i] = 0;
}

__device__ __forceinline__ int edge_dst(const void* ei_raw, int e) {
    if (g_idx64) return (int)((const long long*)ei_raw)[N_EDGES + e];
    return ((const int*)ei_raw)[N_EDGES + e];
}
__device__ __forceinline__ int edge_src(const void* ei_raw, int e) {
    if (g_idx64) return (int)((const long long*)ei_raw)[e];
    return ((const int*)ei_raw)[e];
}

__global__ void hist_kernel(const void* __restrict__ ei_raw) {
    int e = blockIdx.x * blockDim.x + threadIdx.x;
    if (e >= N_EDGES) return;
    int d = edge_dst(ei_raw, e);
    if ((unsigned)d < N_NODES) atomicAdd(&g_deg[d], 1);
}

__global__ void scan1_kernel() {
    __shared__ int ss[256];
    int b = blockIdx.x, t = threadIdx.x;
    int base = b * 1024 + t * 4;
    int v[4], tot = 0;
#pragma unroll
    for (int j = 0; j < 4; j++) {
        v[j] = (base + j < N_NODES) ? g_deg[base + j] : 0;
        tot += v[j];
    }
    ss[t] = tot;
    __syncthreads();
#pragma unroll
    for (int off = 1; off < 256; off <<= 1) {
        int x = (t >= off) ? ss[t - off] : 0;
        __syncthreads();
        ss[t] += x;
        __syncthreads();
    }
    int run = ss[t] - tot;
#pragma unroll
    for (int j = 0; j < 4; j++) {
        if (base + j < N_NODES) g_off[base + j] = run;
        run += v[j];
    }
    if (t == 255) g_bsum[b] = ss[255];
}

__global__ void scan2_kernel() {
    __shared__ int ss[128];
    int t = threadIdx.x;
    int orig = (t < SCAN_BLOCKS) ? g_bsum[t] : 0;
    ss[t] = orig;
    __syncthreads();
#pragma unroll
    for (int off = 1; off < 128; off <<= 1) {
        int x = (t >= off) ? ss[t - off] : 0;
        __syncthreads();
        ss[t] += x;
        __syncthreads();
    }
    if (t < SCAN_BLOCKS) g_boff[t] = ss[t] - orig;
}

__global__ void scan3_kernel() {
    int i = blockIdx.x * blockDim.x + threadIdx.x;
    if (i < N_NODES) {
        int o = g_off[i] + g_boff[i >> 10];
        g_off[i] = o;
        g_cur[i] = o;
    }
    if (i == 0) g_off[N_NODES] = N_EDGES;
}

__global__ void fill_kernel(const void* __restrict__ ei_raw) {
    int e = blockIdx.x * blockDim.x + threadIdx.x;
    if (e >= N_EDGES) return;
    int d = edge_dst(ei_raw, e);
    int s = edge_src(ei_raw, e);
    if ((unsigned)d >= N_NODES || (unsigned)s >= N_NODES) return;
    int p = atomicAdd(&g_cur[d], 1);
    g_srcs[p] = s;
}

// ---------------- per-round aggregation: gather fp32 msg, write split-bf16 agg ----------------
__global__ __launch_bounds__(256) void aggregate_kernel(int node_lo, int node_hi) {
    int node = node_lo + ((blockIdx.x * 256 + threadIdx.x) >> 5);
    int lane = threadIdx.x & 31;
    if (node >= node_hi) return;
    int beg = g_off[node], end = g_off[node + 1];
    float4 acc = make_float4(0.f, 0.f, 0.f, 0.f);
    int e = beg;
    for (; e + 1 < end; e += 2) {
        int s0 = g_srcs[e], s1 = g_srcs[e + 1];
        float4 v0 = *(const float4*)(g_msg + (size_t)s0 * DD + lane * 4);
        float4 v1 = *(const float4*)(g_msg + (size_t)s1 * DD + lane * 4);
        acc.x += v0.x; acc.y += v0.y; acc.z += v0.z; acc.w += v0.w;
        acc.x += v1.x; acc.y += v1.y; acc.z += v1.z; acc.w += v1.w;
    }
    if (e < end) {
        float4 v = *(const float4*)(g_msg + (size_t)g_srcs[e] * DD + lane * 4);
        acc.x += v.x; acc.y += v.y; acc.z += v.z; acc.w += v.w;
    }
    float vv[4] = {acc.x, acc.y, acc.z, acc.w};
    __align__(8) __nv_bfloat16 h[4], l[4];
#pragma unroll
    for (int j = 0; j < 4; j++) {
        h[j] = __float2bfloat16(vv[j]);
        l[j] = __float2bfloat16(vv[j] - __bfloat162float(h[j]));
    }
    __nv_bfloat16* base = g_aggbf + (size_t)node * (2 * DD);
    *(uint2*)(base + lane * 4)      = *(const uint2*)h;   // hi image [0,128)
    *(uint2*)(base + DD + lane * 4) = *(const uint2*)l;   // lo image [128,256)
}

// ---------------- weight precompute: transpose + bf16 split ----------------
__global__ void conv_w_kernel(const float* __restrict__ Wi,
                              const float* __restrict__ Wm,
                              const float* __restrict__ Wu) {
    int m = blockIdx.x;  // 0..8
    const float* W = (m == 0) ? Wi : (m <= 4 ? Wm + (m - 1) * DD * DD : Wu + (m - 5) * DD * DD);
    __nv_bfloat16* hi = g_wb + (size_t)m * 32768;
    __nv_bfloat16* lo = hi + 16384;
    for (int i = threadIdx.x; i < 2048; i += blockDim.x) {
        int nrow = i >> 4;
        int k8   = (i & 15) * 8;
        __align__(16) __nv_bfloat16 h[8], l[8];
#pragma unroll
        for (int j = 0; j < 8; j++) {
            float w = W[(size_t)(k8 + j) * DD + nrow];   // B[n][k] = W[k][n]
            __nv_bfloat16 hb = __float2bfloat16(w);
            h[j] = hb;
            l[j] = __float2bfloat16(w - __bfloat162float(hb));
        }
        *(uint4*)(hi + nrow * DD + k8) = *(const uint4*)h;
        *(uint4*)(lo + nrow * DD + k8) = *(const uint4*)l;
    }
}

// ---------------- helpers (base-target PTX only) ----------------
__device__ __forceinline__ uint32_t smem_u32(const void* p) {
    uint32_t a;
    asm("{ .reg .u64 t; cvta.to.shared.u64 t, %1; cvt.u32.u64 %0, t; }" : "=r"(a) : "l"(p));
    return a;
}
__device__ __forceinline__ void ldsm4(uint32_t* r, uint32_t addr) {
    asm volatile("ldmatrix.sync.aligned.m8n8.x4.shared.b16 {%0,%1,%2,%3}, [%4];"
                 : "=r"(r[0]), "=r"(r[1]), "=r"(r[2]), "=r"(r[3]) : "r"(addr));
}
__device__ __forceinline__ void mma_bf16(float* c,
                                         const uint32_t* a, uint32_t b0, uint32_t b1) {
    asm volatile(
        "mma.sync.aligned.m16n8k16.row.col.f32.bf16.bf16.f32 "
        "{%0,%1,%2,%3}, {%4,%5,%6,%7}, {%8,%9}, {%0,%1,%2,%3};"
        : "+f"(c[0]), "+f"(c[1]), "+f"(c[2]), "+f"(c[3])
        : "r"(a[0]), "r"(a[1]), "r"(a[2]), "r"(a[3]), "r"(b0), "r"(b1));
}
__device__ __forceinline__ void cp_async16(uint32_t smem_addr, const void* gptr) {
    asm volatile("cp.async.ca.shared.global [%0], [%1], 16;"
                 :: "r"(smem_addr), "l"(gptr) : "memory");
}
__device__ __forceinline__ void cp_async16z(uint32_t smem_addr, const void* gptr, unsigned srcsz) {
    asm volatile("cp.async.ca.shared.global [%0], [%1], 16, %2;"
                 :: "r"(smem_addr), "l"(gptr), "r"(srcsz) : "memory");
}

// ---------------- GEMM: 64x128 tile, 2 CTAs/SM, pipelined frags ----------------
#define TILE_M  64
#define BSTR    136
#define A_TB    (TILE_M * BSTR * 2)       // 17408 B
#define B_TB    (128 * BSTR * 2)          // 34816 B
#define SM_BIAS 0
#define SM_AHI  512
#define SM_ALO  (SM_AHI + A_TB)
#define SM_BHI  (SM_ALO + A_TB)
#define SM_BLO  (SM_BHI + B_TB)
#define SM_TOTAL (SM_BLO + B_TB)          // 104960 B -> 2 CTAs/SM

// MODE: 0 fresh / 1 residual (+= state, reconstructed hi+lo from sbf)
// ASRC: 0 = fp32 A (convert in-kernel), 1 = interleaved split-bf16 A via cp.async
// WFP:  write fp32 result to out
// WBF:  write interleaved split-bf16 result to sbf
template <int MODE, int ASRC, int WFP, int WBF>
__global__ __launch_bounds__(256, 2) void gemm_mma_kernel(
    const float* __restrict__ A,
    const __nv_bfloat16* __restrict__ abf,
    const __nv_bfloat16* __restrict__ wb,
    const float* __restrict__ bias,
    float* __restrict__ out,
    __nv_bfloat16* __restrict__ sbf,
    int n, int mb0)
{
    extern __shared__ char smem[];
    const uint32_t sb = smem_u32(smem);
    const int tid = threadIdx.x, wid = tid >> 5, lane = tid & 31;
    const int wr = wid & 1, wc = wid >> 1;      // warp grid 2 (M) x 4 (N)
    const int m0 = (blockIdx.x + mb0) * TILE_M;

    if (tid < 128) *(float*)(smem + SM_BIAS + tid * 4) = bias[tid];

    // ---- B tiles via cp.async ----
    {
        const uint4* srch = (const uint4*)wb;
        const uint4* srcl = (const uint4*)(wb + 16384);
#pragma unroll
        for (int i = tid; i < 2048; i += 256) {
            int row = i >> 4, c = i & 15;
            uint32_t doff = (uint32_t)(row * (BSTR * 2) + c * 16);
            cp_async16(sb + SM_BHI + doff, srch + row * 16 + c);
            cp_async16(sb + SM_BLO + doff, srcl + row * 16 + c);
        }
    }

    if (ASRC == 1) {
        // ---- A tiles: pure cp.async of interleaved split-bf16 (zfill on tail) ----
#pragma unroll
        for (int i = tid; i < 1024; i += 256) {
            int r = i >> 4, c = i & 15;      // c: 16B chunk (8 bf16) within 256B image
            int row = m0 + r;
            int crow = row < n ? row : 0;
            unsigned sz = (row < n) ? 16u : 0u;
            uint32_t doff = (uint32_t)(r * (BSTR * 2) + c * 16);
            const __nv_bfloat16* base = abf + (size_t)crow * (2 * DD) + c * 8;
            cp_async16z(sb + SM_AHI + doff, base, sz);
            cp_async16z(sb + SM_ALO + doff, base + DD, sz);
        }
        asm volatile("cp.async.commit_group;" ::: "memory");
    } else {
        asm volatile("cp.async.commit_group;" ::: "memory");
        // ---- A tile: fp32 -> bf16 hi/lo in-kernel ----
        for (int i = tid; i < TILE_M * 16; i += 256) {
            int r  = i >> 4;
            int k8 = (i & 15) * 8;
            int row = m0 + r;
            float v[8];
            if (row < n) {
                float4 u0 = *(const float4*)(A + (size_t)row * DD + k8);
                float4 u1 = *(const float4*)(A + (size_t)row * DD + k8 + 4);
                v[0] = u0.x; v[1] = u0.y; v[2] = u0.z; v[3] = u0.w;
                v[4] = u1.x; v[5] = u1.y; v[6] = u1.z; v[7] = u1.w;
            } else {
#pragma unroll
                for (int j = 0; j < 8; j++) v[j] = 0.f;
            }
            __align__(16) __nv_bfloat16 h[8], l[8];
#pragma unroll
            for (int j = 0; j < 8; j++) {
                __nv_bfloat16 hb = __float2bfloat16(v[j]);
                h[j] = hb;
                l[j] = __float2bfloat16(v[j] - __bfloat162float(hb));
            }
            *(uint4*)(smem + SM_AHI + r * (BSTR * 2) + k8 * 2) = *(const uint4*)h;
            *(uint4*)(smem + SM_ALO + r * (BSTR * 2) + k8 * 2) = *(const uint4*)l;
        }
    }
    asm volatile("cp.async.wait_group 0;" ::: "memory");
    __syncthreads();

    // ---- mainloop: 8 k-steps, double-buffered frags ----
    float acc[2][4][4];
#pragma unroll
    for (int t = 0; t < 2; t++)
#pragma unroll
        for (int j = 0; j < 4; j++)
#pragma unroll
            for (int q = 0; q < 4; q++)
                acc[t][j][q] = 0.f;

    const uint32_t a_row  = (uint32_t)(wr * 32 + (lane & 15));
    const uint32_t a_colh = (uint32_t)(lane >> 4);
    const uint32_t b_nrow = (uint32_t)(wc * 32 + (lane & 7) + ((lane >> 4) << 3));
    const uint32_t b_kh   = (uint32_t)((lane >> 3) & 1);

    uint32_t ah[2][2][4], al[2][2][4], bh[2][2][4], bl[2][2][4];

#define LOAD_K(ks_, buf_)                                                          \
    {                                                                              \
        const uint32_t kcol = (uint32_t)((ks_) * 16);                              \
        _Pragma("unroll")                                                          \
        for (int t = 0; t < 2; t++) {                                              \
            uint32_t off = (a_row + t * 16) * (BSTR * 2) + (kcol + a_colh * 8) * 2;\
            ldsm4(ah[buf_][t], sb + SM_AHI + off);                                 \
            ldsm4(al[buf_][t], sb + SM_ALO + off);                                 \
        }                                                                          \
        _Pragma("unroll")                                                          \
        for (int p = 0; p < 2; p++) {                                              \
            uint32_t off = (b_nrow + p * 16) * (BSTR * 2) + (kcol + b_kh * 8) * 2; \
            ldsm4(bh[buf_][p], sb + SM_BHI + off);                                 \
            ldsm4(bl[buf_][p], sb + SM_BLO + off);                                 \
        }                                                                          \
    }

    LOAD_K(0, 0)
#pragma unroll
    for (int ks = 0; ks < 8; ks++) {
        const int cur = ks & 1;
        if (ks < 7) LOAD_K(ks + 1, cur ^ 1)
#pragma unroll
        for (int t = 0; t < 2; t++) {
#pragma unroll
            for (int j = 0; j < 4; j++) {
                uint32_t b0h = bh[cur][j >> 1][(j & 1) * 2], b1h = bh[cur][j >> 1][(j & 1) * 2 + 1];
                uint32_t b0l = bl[cur][j >> 1][(j & 1) * 2], b1l = bl[cur][j >> 1][(j & 1) * 2 + 1];
                float* c = acc[t][j];
                mma_bf16(c, ah[cur][t], b0h, b1h);
                mma_bf16(c, ah[cur][t], b0l, b1l);
                mma_bf16(c, al[cur][t], b0h, b1h);
            }
        }
    }
#undef LOAD_K

    // ---- epilogue: bias + relu (+ residual from split-bf16 state), write fp32/bf ----
    const float* bs = (const float*)(smem + SM_BIAS);
#pragma unroll
    for (int t = 0; t < 2; t++) {
        int row0 = m0 + wr * 32 + t * 16 + (lane >> 2);
#pragma unroll
        for (int half = 0; half < 2; half++) {
            int row = row0 + half * 8;
            if (row >= n) continue;
            float* orow = out + (size_t)row * DD;
            __nv_bfloat16* brow = sbf + (size_t)row * (2 * DD);
#pragma unroll
            for (int j = 0; j < 4; j++) {
                int col = wc * 32 + j * 8 + (lane & 3) * 2;
                float v0 = acc[t][j][half * 2 + 0] + bs[col];
                float v1 = acc[t][j][half * 2 + 1] + bs[col + 1];
                v0 = v0 > 0.f ? v0 : 0.f;
                v1 = v1 > 0.f ? v1 : 0.f;
                if (MODE == 1) {
                    __nv_bfloat162 sh = *(const __nv_bfloat162*)(brow + col);
                    __nv_bfloat162 sl = *(const __nv_bfloat162*)(brow + DD + col);
                    float2 shf = __bfloat1622float2(sh);
                    float2 slf = __bfloat1622float2(sl);
                    v0 += shf.x + slf.x;
                    v1 += shf.y + slf.y;
                }
                if (WFP)
                    *(float2*)(orow + col) = make_float2(v0, v1);
                if (WBF) {
                    __nv_bfloat16 h0 = __float2bfloat16(v0);
                    __nv_bfloat16 h1 = __float2bfloat16(v1);
                    __nv_bfloat16 l0 = __float2bfloat16(v0 - __bfloat162float(h0));
                    __nv_bfloat16 l1 = __float2bfloat16(v1 - __bfloat162float(h1));
                    __nv_bfloat16 hh[2] = {h0, h1}, ll[2] = {l0, l1};
                    *(uint32_t*)(brow + col)      = *(const uint32_t*)hh;
                    *(uint32_t*)(brow + DD + col) = *(const uint32_t*)ll;
                }
            }
        }
    }
}

// ---------------- launcher: ONE side stream = CSR build then chunk-B chain ----------------
extern "C" void kernel_launch(void* const* d_in, const int* in_sizes, int n_in,
                              void* d_out, int out_size)
{
    const float* x  = (const float*)d_in[0];
    const void*  ei = d_in[1];
    const float* Wi = (const float*)d_in[2];
    const float* bi = (const float*)d_in[3];
    const float* Wm = (const float*)d_in[4];
    const float* bm = (const float*)d_in[5];
    const float* Wu = (const float*)d_in[6];
    const float* bu = (const float*)d_in[7];
    float* out = (float*)d_out;

    cudaFuncSetAttribute(gemm_mma_kernel<0,0,0,1>, cudaFuncAttributeMaxDynamicSharedMemorySize, SM_TOTAL);
    cudaFuncSetAttribute(gemm_mma_kernel<0,1,1,0>, cudaFuncAttributeMaxDynamicSharedMemorySize, SM_TOTAL);
    cudaFuncSetAttribute(gemm_mma_kernel<1,1,0,1>, cudaFuncAttributeMaxDynamicSharedMemorySize, SM_TOTAL);
    cudaFuncSetAttribute(gemm_mma_kernel<1,1,1,0>, cudaFuncAttributeMaxDynamicSharedMemorySize, SM_TOTAL);

    float* msg;
    __nv_bfloat16 *wb, *aggbf, *statebf;
    cudaGetSymbolAddress((void**)&msg, g_msg);
    cudaGetSymbolAddress((void**)&wb, g_wb);
    cudaGetSymbolAddress((void**)&aggbf, g_aggbf);
    cudaGetSymbolAddress((void**)&statebf, g_statebf);

    const int GRID_FULL = (N_NODES + TILE_M - 1) / TILE_M;   // 1563
    const int AGG_G0 = (CHUNK_ROWS0 * 32 + 255) / 256;
    const int AGG_G1 = ((N_NODES - CHUNK_ROWS0) * 32 + 255) / 256;

    cudaStream_t s3;
    cudaStreamCreateWithFlags(&s3, cudaStreamNonBlocking);
    cudaEvent_t e0, e1, eM0, evA[ROUNDS], evB[ROUNDS];
    cudaEventCreateWithFlags(&e0, cudaEventDisableTiming);
    cudaEventCreateWithFlags(&e1, cudaEventDisableTiming);
    cudaEventCreateWithFlags(&eM0, cudaEventDisableTiming);
    for (int r = 0; r < ROUNDS; r++) {
        cudaEventCreateWithFlags(&evA[r], cudaEventDisableTiming);
        cudaEventCreateWithFlags(&evB[r], cudaEventDisableTiming);
    }

    // ---- side stream: CSR build (overlaps first GEMMs), then chunk-B chain ----
    cudaEventRecord(e0, 0);
    cudaStreamWaitEvent(s3, e0, 0);
    detect_idx_kernel<<<1, 1, 0, s3>>>((const int*)ei);
    hist_zero_kernel<<<(N_NODES + 255) / 256, 256, 0, s3>>>();
    hist_kernel<<<(N_EDGES + 255) / 256, 256, 0, s3>>>(ei);
    scan1_kernel<<<SCAN_BLOCKS, 256, 0, s3>>>();
    scan2_kernel<<<1, 128, 0, s3>>>();
    scan3_kernel<<<(N_NODES + 255) / 256, 256, 0, s3>>>();
    fill_kernel<<<(N_EDGES + 255) / 256, 256, 0, s3>>>(ei);
    cudaEventRecord(e1, s3);            // CSR ready

    // ---- main chain: weights, input GEMM (fp32 A -> statebf), msg GEMM (statebf -> msg) ----
    conv_w_kernel<<<9, 256>>>(Wi, Wm, Wu);
    gemm_mma_kernel<0,0,0,1><<<GRID_FULL, 256, SM_TOTAL>>>(
        x, nullptr, wb, bi, out, statebf, N_NODES, 0);
    gemm_mma_kernel<0,1,1,0><<<GRID_FULL, 256, SM_TOTAL>>>(
        nullptr, statebf, wb + 32768, bm, msg, statebf, N_NODES, 0);

    cudaStreamWaitEvent(0, e1, 0);       // main: CSR must be built before aggregate A
    cudaEventRecord(eM0, 0);
    cudaStreamWaitEvent(s3, eM0, 0);     // s3: msg ready (CSR already done in s3 order)

    for (int r = 0; r < ROUNDS; r++) {
        const bool last = (r + 1 == ROUNDS);
        // chain A (default stream): chunk 0 = rows [0, CHUNK_ROWS0)
        aggregate_kernel<<<AGG_G0, 256>>>(0, CHUNK_ROWS0);
        if (last)
            gemm_mma_kernel<1,1,1,0><<<CHUNK_BLKS0, 256, SM_TOTAL>>>(
                nullptr, aggbf, wb + (size_t)(5 + r) * 32768, bu + r * DD, out, statebf, N_NODES, 0);
        else {
            gemm_mma_kernel<1,1,0,1><<<CHUNK_BLKS0, 256, SM_TOTAL>>>(
                nullptr, aggbf, wb + (size_t)(5 + r) * 32768, bu + r * DD, out, statebf, N_NODES, 0);
            gemm_mma_kernel<0,1,1,0><<<CHUNK_BLKS0, 256, SM_TOTAL>>>(
                nullptr, statebf, wb + (size_t)(2 + r) * 32768, bm + (r + 1) * DD,
                msg, statebf, N_NODES, 0);
        }

        // chain B (s3): chunk 1 = rows [CHUNK_ROWS0, N_NODES)
        aggregate_kernel<<<AGG_G1, 256, 0, s3>>>(CHUNK_ROWS0, N_NODES);
        if (last)
            gemm_mma_kernel<1,1,1,0><<<CHUNK_BLKS1, 256, SM_TOTAL, s3>>>(
                nullptr, aggbf, wb + (size_t)(5 + r) * 32768, bu + r * DD, out, statebf,
                N_NODES, CHUNK_BLKS0);
        else {
            gemm_mma_kernel<1,1,0,1><<<CHUNK_BLKS1, 256, SM_TOTAL, s3>>>(
                nullptr, aggbf, wb + (size_t)(5 + r) * 32768, bu + r * DD, out, statebf,
                N_NODES, CHUNK_BLKS0);
            gemm_mma_kernel<0,1,1,0><<<CHUNK_BLKS1, 256, SM_TOTAL, s3>>>(
                nullptr, statebf, wb + (size_t)(2 + r) * 32768, bm + (r + 1) * DD,
                msg, statebf, N_NODES, CHUNK_BLKS0);
        }

        // join: next round's aggregates read ALL msg rows; final round: out complete on main
        cudaEventRecord(evB[r], s3);
        cudaStreamWaitEvent(0, evB[r], 0);
        if (!last) {
            cudaEventRecord(evA[r], 0);
            cudaStreamWaitEvent(s3, evA[r], 0);
        }
    }
}

// round 17
// speedup vs baseline: 1.1157x; 1.0138x over previous
#include <cuda_runtime.h>
#include <cuda_bf16.h>
#include <cstdint>

#define N_NODES 100000
#define N_EDGES 640000
#define DD      128
#define ROUNDS  4
#define SCAN_BLOCKS 98            // ceil(100000 / 1024)

// chunking: 1563 M-blocks total -> 782 (rows [0,50048)) + 781 (rows [50048,100000))
#define CHUNK_BLKS0 782
#define CHUNK_BLKS1 781
#define CHUNK_ROWS0 50048

// ---------------- scratch (allocation-free rule: __device__ globals) ----------------
__device__ __align__(16) float g_msg[N_NODES * DD];
// agg: interleaved split-bf16, per node 128 hi then 128 lo (512B/node, same as fp32)
__device__ __align__(16) __nv_bfloat16 g_aggbf[N_NODES * 2 * DD];
__device__ __align__(16) __nv_bfloat16 g_wb[9 * 2 * 16384];
__device__ int g_idx64;
// CSR build scratch
__device__ int g_deg[N_NODES];
__device__ int g_off[N_NODES + 1];
__device__ int g_cur[N_NODES];
__device__ int g_srcs[N_EDGES];
__device__ int g_bsum[SCAN_BLOCKS];
__device__ int g_boff[SCAN_BLOCKS];

// ---------------- edge_index dtype detection ----------------
__global__ void detect_idx_kernel(const int* __restrict__ ei32) {
    int is64 = 1;
    for (int i = 0; i < 32; i++) {
        int lo = ei32[2 * i];
        int hi = ei32[2 * i + 1];
        if (hi != 0 || lo < 0 || lo >= N_NODES) { is64 = 0; break; }
    }
    g_idx64 = is64;
}

// ---------------- CSR build (once per call, overlapped with first GEMMs) ----------------
__global__ void hist_zero_kernel() {
    int i = blockIdx.x * blockDim.x + threadIdx.x;
    if (i < N_NODES) g_deg[i] = 0;
}

__device__ __forceinline__ int edge_dst(const void* ei_raw, int e) {
    if (g_idx64) return (int)((const long long*)ei_raw)[N_EDGES + e];
    return ((const int*)ei_raw)[N_EDGES + e];
}
__device__ __forceinline__ int edge_src(const void* ei_raw, int e) {
    if (g_idx64) return (int)((const long long*)ei_raw)[e];
    return ((const int*)ei_raw)[e];
}

__global__ void hist_kernel(const void* __restrict__ ei_raw) {
    int e = blockIdx.x * blockDim.x + threadIdx.x;
    if (e >= N_EDGES) return;
    int d = edge_dst(ei_raw, e);
    if ((unsigned)d < N_NODES) atomicAdd(&g_deg[d], 1);
}

__global__ void scan1_kernel() {
    __shared__ int ss[256];
    int b = blockIdx.x, t = threadIdx.x;
    int base = b * 1024 + t * 4;
    int v[4], tot = 0;
#pragma unroll
    for (int j = 0; j < 4; j++) {
        v[j] = (base + j < N_NODES) ? g_deg[base + j] : 0;
        tot += v[j];
    }
    ss[t] = tot;
    __syncthreads();
#pragma unroll
    for (int off = 1; off < 256; off <<= 1) {
        int x = (t >= off) ? ss[t - off] : 0;
        __syncthreads();
        ss[t] += x;
        __syncthreads();
    }
    int run = ss[t] - tot;
#pragma unroll
    for (int j = 0; j < 4; j++) {
        if (base + j < N_NODES) g_off[base + j] = run;
        run += v[j];
    }
    if (t == 255) g_bsum[b] = ss[255];
}

__global__ void scan2_kernel() {
    __shared__ int ss[128];
    int t = threadIdx.x;
    int orig = (t < SCAN_BLOCKS) ? g_bsum[t] : 0;
    ss[t] = orig;
    __syncthreads();
#pragma unroll
    for (int off = 1; off < 128; off <<= 1) {
        int x = (t >= off) ? ss[t - off] : 0;
        __syncthreads();
        ss[t] += x;
        __syncthreads();
    }
    if (t < SCAN_BLOCKS) g_boff[t] = ss[t] - orig;
}

__global__ void scan3_kernel() {
    int i = blockIdx.x * blockDim.x + threadIdx.x;
    if (i < N_NODES) {
        int o = g_off[i] + g_boff[i >> 10];
        g_off[i] = o;
        g_cur[i] = o;
    }
    if (i == 0) g_off[N_NODES] = N_EDGES;
}

__global__ void fill_kernel(const void* __restrict__ ei_raw) {
    int e = blockIdx.x * blockDim.x + threadIdx.x;
    if (e >= N_EDGES) return;
    int d = edge_dst(ei_raw, e);
    int s = edge_src(ei_raw, e);
    if ((unsigned)d >= N_NODES || (unsigned)s >= N_NODES) return;
    int p = atomicAdd(&g_cur[d], 1);
    g_srcs[p] = s;
}

// ---------------- per-round aggregation: gather fp32 msg, write split-bf16 agg ----------------
__global__ __launch_bounds__(256) void aggregate_kernel(int node_lo, int node_hi) {
    int node = node_lo + ((blockIdx.x * 256 + threadIdx.x) >> 5);
    int lane = threadIdx.x & 31;
    if (node >= node_hi) return;
    int beg = g_off[node], end = g_off[node + 1];
    float4 acc = make_float4(0.f, 0.f, 0.f, 0.f);
    int e = beg;
    for (; e + 1 < end; e += 2) {
        int s0 = g_srcs[e], s1 = g_srcs[e + 1];
        float4 v0 = *(const float4*)(g_msg + (size_t)s0 * DD + lane * 4);
        float4 v1 = *(const float4*)(g_msg + (size_t)s1 * DD + lane * 4);
        acc.x += v0.x; acc.y += v0.y; acc.z += v0.z; acc.w += v0.w;
        acc.x += v1.x; acc.y += v1.y; acc.z += v1.z; acc.w += v1.w;
    }
    if (e < end) {
        float4 v = *(const float4*)(g_msg + (size_t)g_srcs[e] * DD + lane * 4);
        acc.x += v.x; acc.y += v.y; acc.z += v.z; acc.w += v.w;
    }
    float vv[4] = {acc.x, acc.y, acc.z, acc.w};
    __align__(8) __nv_bfloat16 h[4], l[4];
#pragma unroll
    for (int j = 0; j < 4; j++) {
        h[j] = __float2bfloat16(vv[j]);
        l[j] = __float2bfloat16(vv[j] - __bfloat162float(h[j]));
    }
    __nv_bfloat16* base = g_aggbf + (size_t)node * (2 * DD);
    *(uint2*)(base + lane * 4)      = *(const uint2*)h;   // hi image [0,128)
    *(uint2*)(base + DD + lane * 4) = *(const uint2*)l;   // lo image [128,256)
}

// ---------------- weight precompute: transpose + bf16 split ----------------
__global__ void conv_w_kernel(const float* __restrict__ Wi,
                              const float* __restrict__ Wm,
                              const float* __restrict__ Wu) {
    int m = blockIdx.x;  // 0..8
    const float* W = (m == 0) ? Wi : (m <= 4 ? Wm + (m - 1) * DD * DD : Wu + (m - 5) * DD * DD);
    __nv_bfloat16* hi = g_wb + (size_t)m * 32768;
    __nv_bfloat16* lo = hi + 16384;
    for (int i = threadIdx.x; i < 2048; i += blockDim.x) {
        int nrow = i >> 4;
        int k8   = (i & 15) * 8;
        __align__(16) __nv_bfloat16 h[8], l[8];
#pragma unroll
        for (int j = 0; j < 8; j++) {
            float w = W[(size_t)(k8 + j) * DD + nrow];   // B[n][k] = W[k][n]
            __nv_bfloat16 hb = __float2bfloat16(w);
            h[j] = hb;
            l[j] = __float2bfloat16(w - __bfloat162float(hb));
        }
        *(uint4*)(hi + nrow * DD + k8) = *(const uint4*)h;
        *(uint4*)(lo + nrow * DD + k8) = *(const uint4*)l;
    }
}

// ---------------- helpers (base-target PTX only) ----------------
__device__ __forceinline__ uint32_t smem_u32(const void* p) {
    uint32_t a;
    asm("{ .reg .u64 t; cvta.to.shared.u64 t, %1; cvt.u32.u64 %0, t; }" : "=r"(a) : "l"(p));
    return a;
}
__device__ __forceinline__ void ldsm4(uint32_t* r, uint32_t addr) {
    asm volatile("ldmatrix.sync.aligned.m8n8.x4.shared.b16 {%0,%1,%2,%3}, [%4];"
                 : "=r"(r[0]), "=r"(r[1]), "=r"(r[2]), "=r"(r[3]) : "r"(addr));
}
__device__ __forceinline__ void mma_bf16(float* c,
                                         const uint32_t* a, uint32_t b0, uint32_t b1) {
    asm volatile(
        "mma.sync.aligned.m16n8k16.row.col.f32.bf16.bf16.f32 "
        "{%0,%1,%2,%3}, {%4,%5,%6,%7}, {%8,%9}, {%0,%1,%2,%3};"
        : "+f"(c[0]), "+f"(c[1]), "+f"(c[2]), "+f"(c[3])
        : "r"(a[0]), "r"(a[1]), "r"(a[2]), "r"(a[3]), "r"(b0), "r"(b1));
}
__device__ __forceinline__ void cp_async16(uint32_t smem_addr, const void* gptr) {
    asm volatile("cp.async.ca.shared.global [%0], [%1], 16;"
                 :: "r"(smem_addr), "l"(gptr) : "memory");
}
__device__ __forceinline__ void cp_async16z(uint32_t smem_addr, const void* gptr, unsigned srcsz) {
    asm volatile("cp.async.ca.shared.global [%0], [%1], 16, %2;"
                 :: "r"(smem_addr), "l"(gptr), "r"(srcsz) : "memory");
}

// ---------------- GEMM: 64x128 tile, 2 CTAs/SM, pipelined frags ----------------
#define TILE_M  64
#define BSTR    136
#define A_TB    (TILE_M * BSTR * 2)       // 17408 B
#define B_TB    (128 * BSTR * 2)          // 34816 B
#define SM_BIAS 0
#define SM_AHI  512
#define SM_ALO  (SM_AHI + A_TB)
#define SM_BHI  (SM_ALO + A_TB)
#define SM_BLO  (SM_BHI + B_TB)
#define SM_TOTAL (SM_BLO + B_TB)          // 104960 B -> 2 CTAs/SM

// MODE: 0 fresh / 1 residual (out += ...)
// ASRC: 0 = fp32 A (convert in-kernel), 1 = interleaved split-bf16 A via cp.async
template <int MODE, int ASRC>
__global__ __launch_bounds__(256, 2) void gemm_mma_kernel(
    const float* __restrict__ A,
    const __nv_bfloat16* __restrict__ abf,
    const __nv_bfloat16* __restrict__ wb,
    const float* __restrict__ bias,
    float* __restrict__ out,
    int n, int mb0)
{
    extern __shared__ char smem[];
    const uint32_t sb = smem_u32(smem);
    const int tid = threadIdx.x, wid = tid >> 5, lane = tid & 31;
    const int wr = wid & 1, wc = wid >> 1;      // warp grid 2 (M) x 4 (N)
    const int m0 = (blockIdx.x + mb0) * TILE_M;

    if (tid < 128) *(float*)(smem + SM_BIAS + tid * 4) = bias[tid];

    // ---- B tiles via cp.async ----
    {
        const uint4* srch = (const uint4*)wb;
        const uint4* srcl = (const uint4*)(wb + 16384);
#pragma unroll
        for (int i = tid; i < 2048; i += 256) {
            int row = i >> 4, c = i & 15;
            uint32_t doff = (uint32_t)(row * (BSTR * 2) + c * 16);
            cp_async16(sb + SM_BHI + doff, srch + row * 16 + c);
            cp_async16(sb + SM_BLO + doff, srcl + row * 16 + c);
        }
    }

    if (ASRC == 1) {
        // ---- A tiles: pure cp.async of interleaved split-bf16 (zfill on tail) ----
#pragma unroll
        for (int i = tid; i < 1024; i += 256) {
            int r = i >> 4, c = i & 15;      // c: 16B chunk (8 bf16) within 256B image
            int row = m0 + r;
            int crow = row < n ? row : 0;
            unsigned sz = (row < n) ? 16u : 0u;
            uint32_t doff = (uint32_t)(r * (BSTR * 2) + c * 16);
            const __nv_bfloat16* base = abf + (size_t)crow * (2 * DD) + c * 8;
            cp_async16z(sb + SM_AHI + doff, base, sz);
            cp_async16z(sb + SM_ALO + doff, base + DD, sz);
        }
        asm volatile("cp.async.commit_group;" ::: "memory");
    } else {
        asm volatile("cp.async.commit_group;" ::: "memory");
        // ---- A tile: fp32 -> bf16 hi/lo in-kernel ----
        for (int i = tid; i < TILE_M * 16; i += 256) {
            int r  = i >> 4;
            int k8 = (i & 15) * 8;
            int row = m0 + r;
            float v[8];
            if (row < n) {
                float4 u0 = *(const float4*)(A + (size_t)row * DD + k8);
                float4 u1 = *(const float4*)(A + (size_t)row * DD + k8 + 4);
                v[0] = u0.x; v[1] = u0.y; v[2] = u0.z; v[3] = u0.w;
                v[4] = u1.x; v[5] = u1.y; v[6] = u1.z; v[7] = u1.w;
            } else {
#pragma unroll
                for (int j = 0; j < 8; j++) v[j] = 0.f;
            }
            __align__(16) __nv_bfloat16 h[8], l[8];
#pragma unroll
            for (int j = 0; j < 8; j++) {
                __nv_bfloat16 hb = __float2bfloat16(v[j]);
                h[j] = hb;
                l[j] = __float2bfloat16(v[j] - __bfloat162float(hb));
            }
            *(uint4*)(smem + SM_AHI + r * (BSTR * 2) + k8 * 2) = *(const uint4*)h;
            *(uint4*)(smem + SM_ALO + r * (BSTR * 2) + k8 * 2) = *(const uint4*)l;
        }
    }
    asm volatile("cp.async.wait_group 0;" ::: "memory");
    __syncthreads();

    // ---- mainloop: 8 k-steps, double-buffered frags ----
    float acc[2][4][4];
#pragma unroll
    for (int t = 0; t < 2; t++)
#pragma unroll
        for (int j = 0; j < 4; j++)
#pragma unroll
            for (int q = 0; q < 4; q++)
                acc[t][j][q] = 0.f;

    const uint32_t a_row  = (uint32_t)(wr * 32 + (lane & 15));
    const uint32_t a_colh = (uint32_t)(lane >> 4);
    const uint32_t b_nrow = (uint32_t)(wc * 32 + (lane & 7) + ((lane >> 4) << 3));
    const uint32_t b_kh   = (uint32_t)((lane >> 3) & 1);

    uint32_t ah[2][2][4], al[2][2][4], bh[2][2][4], bl[2][2][4];

#define LOAD_K(ks_, buf_)                                                          \
    {                                                                              \
        const uint32_t kcol = (uint32_t)((ks_) * 16);                              \
        _Pragma("unroll")                                                          \
        for (int t = 0; t < 2; t++) {                                              \
            uint32_t off = (a_row + t * 16) * (BSTR * 2) + (kcol + a_colh * 8) * 2;\
            ldsm4(ah[buf_][t], sb + SM_AHI + off);                                 \
            ldsm4(al[buf_][t], sb + SM_ALO + off);                                 \
        }                                                                          \
        _Pragma("unroll")                                                          \
        for (int p = 0; p < 2; p++) {                                              \
            uint32_t off = (b_nrow + p * 16) * (BSTR * 2) + (kcol + b_kh * 8) * 2; \
            ldsm4(bh[buf_][p], sb + SM_BHI + off);                                 \
            ldsm4(bl[buf_][p], sb + SM_BLO + off);                                 \
        }                                                                          \
    }

    LOAD_K(0, 0)
#pragma unroll
    for (int ks = 0; ks < 8; ks++) {
        const int cur = ks & 1;
        if (ks < 7) LOAD_K(ks + 1, cur ^ 1)
#pragma unroll
        for (int t = 0; t < 2; t++) {
#pragma unroll
            for (int j = 0; j < 4; j++) {
                uint32_t b0h = bh[cur][j >> 1][(j & 1) * 2], b1h = bh[cur][j >> 1][(j & 1) * 2 + 1];
                uint32_t b0l = bl[cur][j >> 1][(j & 1) * 2], b1l = bl[cur][j >> 1][(j & 1) * 2 + 1];
                float* c = acc[t][j];
                mma_bf16(c, ah[cur][t], b0h, b1h);
                mma_bf16(c, ah[cur][t], b0l, b1l);
                mma_bf16(c, al[cur][t], b0h, b1h);
            }
        }
    }
#undef LOAD_K

    // ---- epilogue: bias + relu (+ residual) ----
    const float* bs = (const float*)(smem + SM_BIAS);
#pragma unroll
    for (int t = 0; t < 2; t++) {
        int row0 = m0 + wr * 32 + t * 16 + (lane >> 2);
#pragma unroll
        for (int half = 0; half < 2; half++) {
            int row = row0 + half * 8;
            if (row >= n) continue;
            float* orow = out + (size_t)row * DD;
#pragma unroll
            for (int j = 0; j < 4; j++) {
                int col = wc * 32 + j * 8 + (lane & 3) * 2;
                float v0 = acc[t][j][half * 2 + 0] + bs[col];
                float v1 = acc[t][j][half * 2 + 1] + bs[col + 1];
                v0 = v0 > 0.f ? v0 : 0.f;
                v1 = v1 > 0.f ? v1 : 0.f;
                if (MODE == 1) {
                    float2 o = *(const float2*)(orow + col);
                    v0 += o.x; v1 += o.y;
                }
                *(float2*)(orow + col) = make_float2(v0, v1);
            }
        }
    }
}

// ---------------- launcher: chunk-pipelined preamble + round chains, 1 side stream ----------------
extern "C" void kernel_launch(void* const* d_in, const int* in_sizes, int n_in,
                              void* d_out, int out_size)
{
    const float* x  = (const float*)d_in[0];
    const void*  ei = d_in[1];
    const float* Wi = (const float*)d_in[2];
    const float* bi = (const float*)d_in[3];
    const float* Wm = (const float*)d_in[4];
    const float* bm = (const float*)d_in[5];
    const float* Wu = (const float*)d_in[6];
    const float* bu = (const float*)d_in[7];
    float* out = (float*)d_out;

    cudaFuncSetAttribute(gemm_mma_kernel<0,0>, cudaFuncAttributeMaxDynamicSharedMemorySize, SM_TOTAL);
    cudaFuncSetAttribute(gemm_mma_kernel<1,1>, cudaFuncAttributeMaxDynamicSharedMemorySize, SM_TOTAL);

    float* msg;
    __nv_bfloat16 *wb, *aggbf;
    cudaGetSymbolAddress((void**)&msg, g_msg);
    cudaGetSymbolAddress((void**)&wb, g_wb);
    cudaGetSymbolAddress((void**)&aggbf, g_aggbf);

    const int AGG_G0 = (CHUNK_ROWS0 * 32 + 255) / 256;
    const int AGG_G1 = ((N_NODES - CHUNK_ROWS0) * 32 + 255) / 256;

    cudaStream_t s3;
    cudaStreamCreateWithFlags(&s3, cudaStreamNonBlocking);
    cudaEvent_t e0, eW, ePA, ePB, evA[ROUNDS], evB[ROUNDS];
    cudaEventCreateWithFlags(&e0, cudaEventDisableTiming);
    cudaEventCreateWithFlags(&eW, cudaEventDisableTiming);
    cudaEventCreateWithFlags(&ePA, cudaEventDisableTiming);
    cudaEventCreateWithFlags(&ePB, cudaEventDisableTiming);
    for (int r = 0; r < ROUNDS; r++) {
        cudaEventCreateWithFlags(&evA[r], cudaEventDisableTiming);
        cudaEventCreateWithFlags(&evB[r], cudaEventDisableTiming);
    }

    // ---- s3: CSR build; main: conv_w (parallel) ----
    cudaEventRecord(e0, 0);
    cudaStreamWaitEvent(s3, e0, 0);
    detect_idx_kernel<<<1, 1, 0, s3>>>((const int*)ei);
    hist_zero_kernel<<<(N_NODES + 255) / 256, 256, 0, s3>>>();
    hist_kernel<<<(N_EDGES + 255) / 256, 256, 0, s3>>>(ei);
    scan1_kernel<<<SCAN_BLOCKS, 256, 0, s3>>>();
    scan2_kernel<<<1, 128, 0, s3>>>();
    scan3_kernel<<<(N_NODES + 255) / 256, 256, 0, s3>>>();
    fill_kernel<<<(N_EDGES + 255) / 256, 256, 0, s3>>>(ei);

    conv_w_kernel<<<9, 256>>>(Wi, Wm, Wu);
    cudaEventRecord(eW, 0);
    cudaStreamWaitEvent(s3, eW, 0);      // s3 needs weights before its input GEMM chunk

    // ---- chunk-pipelined preamble: input GEMM + first message GEMM ----
    // main: chunk A
    gemm_mma_kernel<0,0><<<CHUNK_BLKS0, 256, SM_TOTAL>>>(x, nullptr, wb, bi, out, N_NODES, 0);
    gemm_mma_kernel<0,0><<<CHUNK_BLKS0, 256, SM_TOTAL>>>(out, nullptr, wb + 32768, bm, msg, N_NODES, 0);
    cudaEventRecord(ePA, 0);
    // s3: chunk B (after CSR + weights)
    gemm_mma_kernel<0,0><<<CHUNK_BLKS1, 256, SM_TOTAL, s3>>>(x, nullptr, wb, bi, out, N_NODES, CHUNK_BLKS0);
    gemm_mma_kernel<0,0><<<CHUNK_BLKS1, 256, SM_TOTAL, s3>>>(out, nullptr, wb + 32768, bm, msg, N_NODES, CHUNK_BLKS0);
    cudaEventRecord(ePB, s3);
    // cross-join: aggregates read ALL msg rows (CSR already done on s3's own chain)
    cudaStreamWaitEvent(0, ePB, 0);
    cudaStreamWaitEvent(s3, ePA, 0);

    for (int r = 0; r < ROUNDS; r++) {
        // chain A (default stream): chunk 0 = rows [0, CHUNK_ROWS0)
        aggregate_kernel<<<AGG_G0, 256>>>(0, CHUNK_ROWS0);
        gemm_mma_kernel<1,1><<<CHUNK_BLKS0, 256, SM_TOTAL>>>(
            nullptr, aggbf, wb + (size_t)(5 + r) * 32768, bu + r * DD, out, N_NODES, 0);
        if (r + 1 < ROUNDS)
            gemm_mma_kernel<0,0><<<CHUNK_BLKS0, 256, SM_TOTAL>>>(
                out, nullptr, wb + (size_t)(2 + r) * 32768, bm + (r + 1) * DD, msg, N_NODES, 0);

        // chain B (s3): chunk 1 = rows [CHUNK_ROWS0, N_NODES)
        aggregate_kernel<<<AGG_G1, 256, 0, s3>>>(CHUNK_ROWS0, N_NODES);
        gemm_mma_kernel<1,1><<<CHUNK_BLKS1, 256, SM_TOTAL, s3>>>(
            nullptr, aggbf, wb + (size_t)(5 + r) * 32768, bu + r * DD, out, N_NODES, CHUNK_BLKS0);
        if (r + 1 < ROUNDS)
            gemm_mma_kernel<0,0><<<CHUNK_BLKS1, 256, SM_TOTAL, s3>>>(
                out, nullptr, wb + (size_t)(2 + r) * 32768, bm + (r + 1) * DD, msg, N_NODES, CHUNK_BLKS0);

        // join: next round's aggregates read ALL msg rows; final round: out complete on main
        cudaEventRecord(evB[r], s3);
        cudaStreamWaitEvent(0, evB[r], 0);
        if (r + 1 < ROUNDS) {
            cudaEventRecord(evA[r], 0);
            cudaStreamWaitEvent(s3, evA[r], 0);
        }
    }
}